// round 1
// baseline (speedup 1.0000x reference)
#include <cuda_runtime.h>
#include <cuda_bf16.h>

// Problem constants (fixed by the dataset: B=2048, N=64, F=19)
static constexpr int BATCH = 2048;
static constexpr int NSLOT = 64;
static constexpr int FEAT  = 19;

// Scratch: per-batch partial losses (no device allocation allowed -> __device__ global)
__device__ float g_partials[BATCH];

// One CTA per batch. threadIdx.x = row index i (also doubles as column index j
// for the reverse-argmax pass). Emulates the reference's greedy mutual-best
// matching exactly, including first-occurrence argmax tie-breaking.
__global__ __launch_bounds__(NSLOT) void spotting_match_loss_kernel(
    const float* __restrict__ y_true,
    const float* __restrict__ y_pred)
{
    const int b = blockIdx.x;
    const int i = threadIdx.x;

    __shared__ float         sp[NSLOT];        // p_j = y_pred[:, j, 1]
    __shared__ float         sbestval[NSLOT];  // row i's best D1 value this round
    __shared__ int           sbestj[NSLOT];    // row i's chosen column this round
    __shared__ int           sperm[NSLOT];     // final assignment row -> column
    __shared__ unsigned char staken[NSLOT];    // column taken flag
    __shared__ float         sred[NSLOT];      // loss reduction buffer

    const float* yt = y_true + (size_t)b * NSLOT * FEAT;
    const float* yp = y_pred + (size_t)b * NSLOT * FEAT;

    const float a  = yt[i * FEAT + 0];   // alpha in {0,1}
    const float xi = yt[i * FEAT + 1];   // x_i

    sp[i]     = yp[i * FEAT + 1];        // p_i
    sperm[i]  = -1;
    staken[i] = 0;
    __syncthreads();

    // Phase 0: rows with alpha==1, Phase 1: rows with alpha==0.
    // Columns taken in phase 0 stay taken in phase 1 (matches h carrying over).
    for (int phase = 0; phase < 2; ++phase) {
        const bool in_phase = (phase == 0) ? (a > 0.5f) : (a <= 0.5f);

        for (int iter = 0; iter < NSLOT; ++iter) {
            const bool active = in_phase && (sperm[i] < 0);
            // All rows of this phase assigned -> phase done (extra reference
            // iterations are no-ops once v == 0).
            if (__syncthreads_and(!active)) break;

            // --- Row argmax over free columns: D1[i][j] = 1 - |x_i - p_j| ---
            // All D1 entries are strictly > 0 for this data, masked columns
            // contribute 0 in the reference, so scanning only free columns with
            // strict '>' (first-index tie-break) matches jnp.argmax exactly.
            float bv = -1.0f;
            int   bj = -1;
            if (active) {
                #pragma unroll 4
                for (int j = 0; j < NSLOT; ++j) {
                    if (!staken[j]) {
                        const float d = 1.0f - fabsf(xi - sp[j]);
                        if (d > bv) { bv = d; bj = j; }
                    }
                }
            }
            sbestval[i] = bv;
            sbestj[i]   = active ? bj : -1;
            __syncthreads();

            // --- Column argmax: thread i acts as column j=i. Among rows that
            // picked this column, take max value, lowest row index on ties. ---
            int   win = -1;
            float wv  = -1.0f;
            if (!staken[i]) {
                #pragma unroll 4
                for (int r = 0; r < NSLOT; ++r) {
                    if (sbestj[r] == i) {
                        const float v = sbestval[r];
                        if (v > wv) { wv = v; win = r; }
                    }
                }
            }
            // Mutual pair (row win, col i): assign. Each row is picked by at
            // most one column (it has a single bestj), so no write conflicts.
            if (win >= 0) {
                sperm[win] = i;
                staken[i]  = 1;
            }
            __syncthreads();
        }
    }

    // --- Loss contribution of row i using permuted prediction ---
    const int    pi  = sperm[i];
    const float* ypp = yp + (size_t)pi * FEAT;

    float l;
    {
        const float yp0 = ypp[0];
        const float yp1 = ypp[1];
        const float d1  = xi - yp1;
        const float d0  = a - yp0;
        l = a * 5.0f * d1 * d1            // LAMBDA_COORD coord term
          + a * d0 * d0                   // obj confidence term
          + (1.0f - a) * 0.5f * d0 * d0;  // LAMBDA_NOOBJ term
        float s2 = 0.0f;
        #pragma unroll
        for (int f = 2; f < FEAT; ++f) {
            const float d = yt[i * FEAT + f] - ypp[f];
            s2 += d * d;
        }
        l += a * s2;
    }

    // Deterministic block tree-reduce
    sred[i] = l;
    __syncthreads();
    #pragma unroll
    for (int off = NSLOT / 2; off > 0; off >>= 1) {
        if (i < off) sred[i] += sred[i + off];
        __syncthreads();
    }
    if (i == 0) g_partials[b] = sred[0];
}

// Deterministic final reduce: fixed-order sequential sums + fixed tree.
__global__ __launch_bounds__(256) void spotting_reduce_kernel(float* __restrict__ out)
{
    __shared__ float s[256];
    const int t = threadIdx.x;
    float v = 0.0f;
    // Each thread sums 8 partials in a fixed order.
    #pragma unroll
    for (int k = 0; k < BATCH / 256; ++k) {
        v += g_partials[t + k * 256];
    }
    s[t] = v;
    __syncthreads();
    #pragma unroll
    for (int off = 128; off > 0; off >>= 1) {
        if (t < off) s[t] += s[t + off];
        __syncthreads();
    }
    if (t == 0) out[0] = s[0];
}

extern "C" void kernel_launch(void* const* d_in, const int* in_sizes, int n_in,
                              void* d_out, int out_size)
{
    const float* y_true = (const float*)d_in[0];
    const float* y_pred = (const float*)d_in[1];
    float*       out    = (float*)d_out;

    spotting_match_loss_kernel<<<BATCH, NSLOT>>>(y_true, y_pred);
    spotting_reduce_kernel<<<1, 256>>>(out);
}

// round 2
// speedup vs baseline: 2.5374x; 2.5374x over previous
#include <cuda_runtime.h>
#include <cuda_bf16.h>

// Problem constants (fixed by the dataset: B=2048, N=64, F=19)
static constexpr int BATCH = 2048;
static constexpr int NSLOT = 64;
static constexpr int FEAT  = 19;

// Scratch (no device allocation allowed -> __device__ globals)
__device__ float g_partials[BATCH];
__device__ int   g_count = 0;   // self-resetting -> graph-replay safe

// One CTA per batch. threadIdx.x = row index i (doubles as column index for the
// acceptance step). Exactly reproduces the reference greedy mutual-best
// matching, including first-occurrence argmax tie-breaking.
__global__ __launch_bounds__(NSLOT) void spotting_match_loss_kernel(
    const float* __restrict__ y_true,
    const float* __restrict__ y_pred,
    float*       __restrict__ out)
{
    const int b = blockIdx.x;
    const int i = threadIdx.x;

    __shared__ float              sp[NSLOT];      // p_j; taken columns -> 1e30
    __shared__ unsigned long long colkey[NSLOT];  // best proposal per column
    __shared__ int                srow2col[NSLOT];// final assignment row -> col
    __shared__ float              sred[NSLOT];
    __shared__ int                sflag;

    const float* yt = y_true + (size_t)b * NSLOT * FEAT;
    const float* yp = y_pred + (size_t)b * NSLOT * FEAT;

    const float a  = yt[i * FEAT + 0];   // alpha in {0,1}
    const float xi = yt[i * FEAT + 1];   // x_i

    sp[i]       = yp[i * FEAT + 1];      // p_i
    srow2col[i] = -1;
    colkey[i]   = 0ULL;
    __syncthreads();

    // Phase 0: alpha==1 rows; Phase 1: alpha==0 rows. Columns taken in phase 0
    // stay removed (sp[col] = 1e30) for phase 1, matching h carry-over.
    #pragma unroll 1
    for (int phase = 0; phase < 2; ++phase) {
        const bool in_phase = (phase == 0) ? (a > 0.5f) : (a <= 0.5f);

        for (;;) {
            const bool active = in_phase && (srow2col[i] < 0);
            if (__syncthreads_and(!active)) break;

            if (active) {
                // Row argmax over D1[i][j] = 1 - |x_i - p_j|. Taken columns
                // have p_j = 1e30 -> d = -1e30, never selected (a free column
                // with d > 0 always exists while this row is active). Strict
                // '>' gives first-occurrence (lowest j) tie-break, matching
                // jnp.argmax.
                float bv = -3e38f;
                int   bj = 0;
                #pragma unroll
                for (int j = 0; j < NSLOT; ++j) {
                    const float d = 1.0f - fabsf(xi - sp[j]);
                    if (d > bv) { bv = d; bj = j; }
                }
                // Propose: pack (value desc, row asc) into one monotonic key.
                // bv > 0 here, so bits(bv) < 2^30 and key != 0.
                const unsigned long long key =
                    ((unsigned long long)__float_as_uint(bv) << 6) |
                    (unsigned long long)(63 - i);
                atomicMax(&colkey[bj], key);
            }
            __syncthreads();

            // Column role: any column with >=1 proposal accepts its best
            // proposer (max value, lowest row). This is exactly E = v*A*C.
            const unsigned long long k = colkey[i];
            if (k) {
                const int r = 63 - (int)(k & 63ULL);
                srow2col[r] = i;       // unique writer: only r's bestj sees r win
                sp[i]       = 1e30f;   // remove column from future argmaxes
                colkey[i]   = 0ULL;    // reset for next round
            }
            __syncthreads();
        }
    }

    // --- Loss contribution of row i against permuted prediction ---
    const int    pi  = srow2col[i];
    const float* ypp = yp + (size_t)pi * FEAT;

    float l;
    {
        const float yp0 = ypp[0];
        const float yp1 = ypp[1];
        const float d1  = xi - yp1;
        const float d0  = a - yp0;
        l = a * 5.0f * d1 * d1            // LAMBDA_COORD coord term
          + a * d0 * d0                   // obj confidence term
          + (1.0f - a) * 0.5f * d0 * d0;  // LAMBDA_NOOBJ term
        float s2 = 0.0f;
        #pragma unroll
        for (int f = 2; f < FEAT; ++f) {
            const float d = yt[i * FEAT + f] - ypp[f];
            s2 += d * d;
        }
        l += a * s2;
    }

    // Deterministic per-block tree reduce
    sred[i] = l;
    __syncthreads();
    #pragma unroll
    for (int off = NSLOT / 2; off > 0; off >>= 1) {
        if (i < off) sred[i] += sred[i + off];
        __syncthreads();
    }

    // Publish partial; last CTA to finish performs the (fixed-order,
    // deterministic) global reduction. Counter self-resets for graph replay.
    if (i == 0) {
        g_partials[b] = sred[0];
        __threadfence();
        const int t = atomicAdd(&g_count, 1);
        sflag = (t == BATCH - 1);
    }
    __syncthreads();

    if (sflag) {
        float v = 0.0f;
        #pragma unroll
        for (int k = 0; k < BATCH / NSLOT; ++k) {
            v += g_partials[i + k * NSLOT];   // fixed order per thread
        }
        sred[i] = v;
        __syncthreads();
        #pragma unroll
        for (int off = NSLOT / 2; off > 0; off >>= 1) {
            if (i < off) sred[i] += sred[i + off];
            __syncthreads();
        }
        if (i == 0) {
            out[0]  = sred[0];
            g_count = 0;   // reset for next graph replay
        }
    }
}

extern "C" void kernel_launch(void* const* d_in, const int* in_sizes, int n_in,
                              void* d_out, int out_size)
{
    const float* y_true = (const float*)d_in[0];
    const float* y_pred = (const float*)d_in[1];
    float*       out    = (float*)d_out;

    spotting_match_loss_kernel<<<BATCH, NSLOT>>>(y_true, y_pred, out);
}